// round 1
// baseline (speedup 1.0000x reference)
#include <cuda_runtime.h>

#define TOKENS 8192
#define FEAT   4096

// scratch for h2 (8192 x 64 fp32) -- no allocations allowed, use device global
__device__ __align__(16) float g_h2[TOKENS * 64];

// ---------------------------------------------------------------------------
// Kernel 1: smooth-scale, NVFP4 fake-quant (block=16), contract C then B.
//   h2[t, r] = sum_i b_q[i,r] * ( sum_j xq[t, i*64+j] * c_q_t[r, j] )
// One token per block-iteration; 256 threads = 16x16 (ti, tr), each owning a
// 4x4 tile of the 64x64 h1 intermediate in registers.
// ---------------------------------------------------------------------------
__global__ void __launch_bounds__(256) k1_quant_contract(
    const float* __restrict__ x,
    const float* __restrict__ smooth,
    const float* __restrict__ b_q,
    const float* __restrict__ c_q_t)
{
    __shared__ float csT[64 * 64];   // csT[j*64 + r] = c_q_t[r*64 + j]
    __shared__ float xqT[64 * 64];   // xqT[j*64 + i] = xq[i*64 + j]
    __shared__ float red[16 * 64];   // partial h2 sums per ti-group

    const int t = threadIdx.x;

    // preload transposed C
    for (int idx = t; idx < 4096; idx += 256) {
        int r = idx >> 6, j = idx & 63;
        csT[j * 64 + r] = c_q_t[idx];
    }

    // each thread owns one 16-element quant block per token: elements t*16 .. t*16+15
    float sm[16];
#pragma unroll
    for (int k = 0; k < 4; k++) {
        float4 v = reinterpret_cast<const float4*>(smooth)[t * 4 + k];
        sm[4 * k + 0] = v.x; sm[4 * k + 1] = v.y;
        sm[4 * k + 2] = v.z; sm[4 * k + 3] = v.w;
    }
    __syncthreads();

    const int ti  = t >> 4;          // 0..15 : i-tile
    const int tr  = t & 15;          // 0..15 : r-tile
    const int qi  = t >> 2;          // quant store: row i = t/4
    const int qj0 = (t & 3) * 16;    // quant store: starting j

    for (int tok = blockIdx.x; tok < TOKENS; tok += gridDim.x) {
        // ---- load + smooth ----
        const float4* xt = reinterpret_cast<const float4*>(x + (size_t)tok * FEAT);
        float y[16];
#pragma unroll
        for (int k = 0; k < 4; k++) {
            float4 v = xt[t * 4 + k];
            y[4 * k + 0] = v.x * sm[4 * k + 0];
            y[4 * k + 1] = v.y * sm[4 * k + 1];
            y[4 * k + 2] = v.z * sm[4 * k + 2];
            y[4 * k + 3] = v.w * sm[4 * k + 3];
        }

        // ---- NVFP4 fake-quant (amax -> scale -> round-to-grid -> dequant) ----
        float amax = 0.0f;
#pragma unroll
        for (int k = 0; k < 16; k++) amax = fmaxf(amax, fabsf(y[k]));
        float scale = fmaxf(amax / 6.0f, 1e-8f);
        float inv = 1.0f / scale;
#pragma unroll
        for (int k = 0; k < 16; k++) {
            float av = fabsf(y[k]) * inv;
            // mids: 0.25 0.75 1.25 1.75 2.5 3.5 5.0  (ties go up, searchsorted 'right')
            float q;
            q = (av <  0.25f) ? 0.0f : 0.5f;
            q = (av >= 0.75f) ? 1.0f : q;
            q = (av >= 1.25f) ? 1.5f : q;
            q = (av >= 1.75f) ? 2.0f : q;
            q = (av >= 2.5f)  ? 3.0f : q;
            q = (av >= 3.5f)  ? 4.0f : q;
            q = (av >= 5.0f)  ? 6.0f : q;
            xqT[(qj0 + k) * 64 + qi] = copysignf(q * scale, y[k]);
        }
        __syncthreads();

        // ---- stage A: h1[i, r] = sum_j xq[i, j] * C[r, j] ----
        float acc[4][4];
#pragma unroll
        for (int a = 0; a < 4; a++)
#pragma unroll
            for (int c = 0; c < 4; c++) acc[a][c] = 0.0f;

#pragma unroll 4
        for (int j = 0; j < 64; j++) {
            float4 xv = *reinterpret_cast<const float4*>(&xqT[j * 64 + ti * 4]);
            float4 cv = *reinterpret_cast<const float4*>(&csT[j * 64 + tr * 4]);
            acc[0][0] += xv.x * cv.x; acc[0][1] += xv.x * cv.y;
            acc[0][2] += xv.x * cv.z; acc[0][3] += xv.x * cv.w;
            acc[1][0] += xv.y * cv.x; acc[1][1] += xv.y * cv.y;
            acc[1][2] += xv.y * cv.z; acc[1][3] += xv.y * cv.w;
            acc[2][0] += xv.z * cv.x; acc[2][1] += xv.z * cv.y;
            acc[2][2] += xv.z * cv.z; acc[2][3] += xv.z * cv.w;
            acc[3][0] += xv.w * cv.x; acc[3][1] += xv.w * cv.y;
            acc[3][2] += xv.w * cv.z; acc[3][3] += xv.w * cv.w;
        }

        // ---- stage B: weight by b_q and partially reduce over i ----
        float4 p = make_float4(0.f, 0.f, 0.f, 0.f);
#pragma unroll
        for (int a = 0; a < 4; a++) {
            float4 bv = __ldg(reinterpret_cast<const float4*>(&b_q[(ti * 4 + a) * 64 + tr * 4]));
            p.x += acc[a][0] * bv.x;
            p.y += acc[a][1] * bv.y;
            p.z += acc[a][2] * bv.z;
            p.w += acc[a][3] * bv.w;
        }
        *reinterpret_cast<float4*>(&red[ti * 64 + tr * 4]) = p;
        __syncthreads();

        if (t < 64) {
            float s = 0.0f;
#pragma unroll
            for (int g = 0; g < 16; g++) s += red[g * 64 + t];
            g_h2[tok * 64 + t] = s;
        }
        // no third sync needed: next iteration's SMEM writes are ordered by the
        // next __syncthreads() before any thread reads them again.
    }
}

// ---------------------------------------------------------------------------
// Kernel 2: out[t, m] = sum_r h2[t, r] * a_q[m, r] + bias[m]
// 128 x 128 output tile per block, K=64 in two 32-wide SMEM stages,
// 8x8 register micro-tile per thread.
// ---------------------------------------------------------------------------
__global__ void __launch_bounds__(256) k2_expand(
    const float* __restrict__ a_q,
    const float* __restrict__ bias,
    float* __restrict__ out)
{
    __shared__ float AsT[32 * 128];  // AsT[k*128 + tt] = h2[t0+tt, ks+k]
    __shared__ float BsT[32 * 128];  // BsT[k*128 + mm] = a_q[m0+mm, ks+k]

    const int t  = threadIdx.x;
    const int tx = t & 15;   // m micro-tile
    const int ty = t >> 4;   // token micro-tile
    const int m0 = blockIdx.x * 128;
    const int t0 = blockIdx.y * 128;

    const int ltt = t & 127; // row handled during loads
    const int lk  = t >> 7;  // 0 or 1

    float acc[8][8];
#pragma unroll
    for (int u = 0; u < 8; u++)
#pragma unroll
        for (int v = 0; v < 8; v++) acc[u][v] = 0.0f;

    for (int ks = 0; ks < 64; ks += 32) {
        __syncthreads();   // protect previous stage's SMEM before overwrite
#pragma unroll
        for (int it = 0; it < 4; it++) {
            int kq = lk + it * 2;  // 0..7, covers 32 k as 8 float4 groups
            float4 hv = *reinterpret_cast<const float4*>(&g_h2[(t0 + ltt) * 64 + ks + kq * 4]);
            AsT[(kq * 4 + 0) * 128 + ltt] = hv.x;
            AsT[(kq * 4 + 1) * 128 + ltt] = hv.y;
            AsT[(kq * 4 + 2) * 128 + ltt] = hv.z;
            AsT[(kq * 4 + 3) * 128 + ltt] = hv.w;
            float4 av = __ldg(reinterpret_cast<const float4*>(&a_q[(size_t)(m0 + ltt) * 64 + ks + kq * 4]));
            BsT[(kq * 4 + 0) * 128 + ltt] = av.x;
            BsT[(kq * 4 + 1) * 128 + ltt] = av.y;
            BsT[(kq * 4 + 2) * 128 + ltt] = av.z;
            BsT[(kq * 4 + 3) * 128 + ltt] = av.w;
        }
        __syncthreads();

#pragma unroll 8
        for (int k = 0; k < 32; k++) {
            float4 a0 = *reinterpret_cast<const float4*>(&AsT[k * 128 + ty * 8]);
            float4 a1 = *reinterpret_cast<const float4*>(&AsT[k * 128 + ty * 8 + 4]);
            float4 b0 = *reinterpret_cast<const float4*>(&BsT[k * 128 + tx * 8]);
            float4 b1 = *reinterpret_cast<const float4*>(&BsT[k * 128 + tx * 8 + 4]);
            float ar[8] = {a0.x, a0.y, a0.z, a0.w, a1.x, a1.y, a1.z, a1.w};
            float br[8] = {b0.x, b0.y, b0.z, b0.w, b1.x, b1.y, b1.z, b1.w};
#pragma unroll
            for (int u = 0; u < 8; u++)
#pragma unroll
                for (int v = 0; v < 8; v++)
                    acc[u][v] += ar[u] * br[v];
        }
    }

    // epilogue: + bias, float4 stores
    float4 bb0 = __ldg(reinterpret_cast<const float4*>(&bias[m0 + tx * 8]));
    float4 bb1 = __ldg(reinterpret_cast<const float4*>(&bias[m0 + tx * 8 + 4]));
#pragma unroll
    for (int u = 0; u < 8; u++) {
        float* orow = out + (size_t)(t0 + ty * 8 + u) * FEAT + m0 + tx * 8;
        float4 o0 = make_float4(acc[u][0] + bb0.x, acc[u][1] + bb0.y,
                                acc[u][2] + bb0.z, acc[u][3] + bb0.w);
        float4 o1 = make_float4(acc[u][4] + bb1.x, acc[u][5] + bb1.y,
                                acc[u][6] + bb1.z, acc[u][7] + bb1.w);
        *reinterpret_cast<float4*>(orow)     = o0;
        *reinterpret_cast<float4*>(orow + 4) = o1;
    }
}

extern "C" void kernel_launch(void* const* d_in, const int* in_sizes, int n_in,
                              void* d_out, int out_size) {
    const float* x      = (const float*)d_in[0];  // (4, 2048, 4096)
    const float* smooth = (const float*)d_in[1];  // (4096,)
    const float* a_q    = (const float*)d_in[2];  // (4096, 64)
    const float* b_q    = (const float*)d_in[3];  // (64, 64)
    const float* c_q_t  = (const float*)d_in[4];  // (64, 64)
    const float* bias   = (const float*)d_in[5];  // (4096,)
    float* out          = (float*)d_out;          // (4, 2048, 4096)

    k1_quant_contract<<<1024, 256>>>(x, smooth, b_q, c_q_t);
    k2_expand<<<dim3(32, 64), 256>>>(a_q, bias, out);
}

// round 2
// speedup vs baseline: 1.0110x; 1.0110x over previous
#include <cuda_runtime.h>

#define TOKENS 8192
#define FEAT   4096

// scratch for h2 (8192 x 64 fp32)
__device__ __align__(16) float g_h2[TOKENS * 64];

// ---------------------------------------------------------------------------
// Packed dual-fp32 helpers (sm_103a f32x2 pipe; 2 MACs per FMA issue)
// ---------------------------------------------------------------------------
__device__ __forceinline__ unsigned long long ffma2(unsigned long long a,
                                                    unsigned long long b,
                                                    unsigned long long c) {
    unsigned long long d;
    asm("fma.rn.f32x2 %0, %1, %2, %3;" : "=l"(d) : "l"(a), "l"(b), "l"(c));
    return d;
}
__device__ __forceinline__ unsigned long long dup2(float x) {
    unsigned long long r;
    asm("mov.b64 %0, {%1, %1};" : "=l"(r) : "f"(x));
    return r;
}
__device__ __forceinline__ float2 unpack2(unsigned long long v) {
    float lo, hi;
    asm("mov.b64 {%0, %1}, %2;" : "=f"(lo), "=f"(hi) : "l"(v));
    return make_float2(lo, hi);
}

// ---------------------------------------------------------------------------
// Kernel 1: smooth-scale, NVFP4 fake-quant (block=16), contract C then B.
//   h2[t, r] = sum_i b_q[i,r] * ( sum_j xq[t, i*64+j] * c_q_t[r, j] )
// ---------------------------------------------------------------------------
__global__ void __launch_bounds__(256) k1_quant_contract(
    const float* __restrict__ x,
    const float* __restrict__ smooth,
    const float* __restrict__ b_q,
    const float* __restrict__ c_q_t)
{
    __shared__ float csT[64 * 64];   // csT[j*64 + r] = c_q_t[r*64 + j]
    __shared__ float xqT[64 * 64];   // xqT[j*64 + i] = xq[i*64 + j]
    __shared__ float red[16 * 64];   // partial h2 sums per ti-group

    const int t = threadIdx.x;

    // preload transposed C
    for (int idx = t; idx < 4096; idx += 256) {
        int r = idx >> 6, j = idx & 63;
        csT[j * 64 + r] = c_q_t[idx];
    }

    // each thread owns one 16-element quant block per token
    float sm[16];
#pragma unroll
    for (int k = 0; k < 4; k++) {
        float4 v = reinterpret_cast<const float4*>(smooth)[t * 4 + k];
        sm[4 * k + 0] = v.x; sm[4 * k + 1] = v.y;
        sm[4 * k + 2] = v.z; sm[4 * k + 3] = v.w;
    }
    __syncthreads();

    const int ti  = t >> 4;          // 0..15 : i-tile
    const int tr  = t & 15;          // 0..15 : r-tile
    const int qi  = t >> 2;          // quant store: row i = t/4
    const int qj0 = (t & 3) * 16;    // quant store: starting j

    for (int tok = blockIdx.x; tok < TOKENS; tok += gridDim.x) {
        // ---- load + smooth ----
        const float4* xt = reinterpret_cast<const float4*>(x + (size_t)tok * FEAT);
        float y[16];
#pragma unroll
        for (int k = 0; k < 4; k++) {
            float4 v = xt[t * 4 + k];
            y[4 * k + 0] = v.x * sm[4 * k + 0];
            y[4 * k + 1] = v.y * sm[4 * k + 1];
            y[4 * k + 2] = v.z * sm[4 * k + 2];
            y[4 * k + 3] = v.w * sm[4 * k + 3];
        }

        // ---- NVFP4 fake-quant ----
        float amax = 0.0f;
#pragma unroll
        for (int k = 0; k < 16; k++) amax = fmaxf(amax, fabsf(y[k]));
        float scale = fmaxf(amax / 6.0f, 1e-8f);
        float inv = 1.0f / scale;
#pragma unroll
        for (int k = 0; k < 16; k++) {
            float av = fabsf(y[k]) * inv;
            float q;
            q = (av <  0.25f) ? 0.0f : 0.5f;
            q = (av >= 0.75f) ? 1.0f : q;
            q = (av >= 1.25f) ? 1.5f : q;
            q = (av >= 1.75f) ? 2.0f : q;
            q = (av >= 2.5f)  ? 3.0f : q;
            q = (av >= 3.5f)  ? 4.0f : q;
            q = (av >= 5.0f)  ? 6.0f : q;
            xqT[(qj0 + k) * 64 + qi] = copysignf(q * scale, y[k]);
        }
        __syncthreads();

        // ---- stage A: h1[i, r] = sum_j xq[i, j] * C[r, j] (packed f32x2) ----
        unsigned long long acc2[4][2];
#pragma unroll
        for (int a = 0; a < 4; a++) { acc2[a][0] = 0ull; acc2[a][1] = 0ull; }

#pragma unroll 4
        for (int j = 0; j < 64; j++) {
            float4 xv = *reinterpret_cast<const float4*>(&xqT[j * 64 + ti * 4]);
            ulonglong2 cv = *reinterpret_cast<const ulonglong2*>(&csT[j * 64 + tr * 4]);
            unsigned long long x0 = dup2(xv.x), x1 = dup2(xv.y);
            unsigned long long x2 = dup2(xv.z), x3 = dup2(xv.w);
            acc2[0][0] = ffma2(x0, cv.x, acc2[0][0]);
            acc2[0][1] = ffma2(x0, cv.y, acc2[0][1]);
            acc2[1][0] = ffma2(x1, cv.x, acc2[1][0]);
            acc2[1][1] = ffma2(x1, cv.y, acc2[1][1]);
            acc2[2][0] = ffma2(x2, cv.x, acc2[2][0]);
            acc2[2][1] = ffma2(x2, cv.y, acc2[2][1]);
            acc2[3][0] = ffma2(x3, cv.x, acc2[3][0]);
            acc2[3][1] = ffma2(x3, cv.y, acc2[3][1]);
        }

        // ---- stage B: weight by b_q and partially reduce over i (packed) ----
        unsigned long long p0 = 0ull, p1 = 0ull;
#pragma unroll
        for (int a = 0; a < 4; a++) {
            ulonglong2 bv = *reinterpret_cast<const ulonglong2*>(&b_q[(ti * 4 + a) * 64 + tr * 4]);
            p0 = ffma2(acc2[a][0], bv.x, p0);
            p1 = ffma2(acc2[a][1], bv.y, p1);
        }
        ulonglong2 pr; pr.x = p0; pr.y = p1;
        *reinterpret_cast<ulonglong2*>(&red[ti * 64 + tr * 4]) = pr;
        __syncthreads();

        if (t < 64) {
            float s = 0.0f;
#pragma unroll
            for (int g = 0; g < 16; g++) s += red[g * 64 + t];
            g_h2[tok * 64 + t] = s;
        }
    }
}

// ---------------------------------------------------------------------------
// Kernel 2: out[t, m] = sum_r h2[t, r] * a_q[m, r] + bias[m]
// 128x128 tile, 8x8 micro-tile, packed f32x2 outer product.
// ---------------------------------------------------------------------------
__global__ void __launch_bounds__(256) k2_expand(
    const float* __restrict__ a_q,
    const float* __restrict__ bias,
    float* __restrict__ out)
{
    __shared__ float AsT[32 * 128];  // AsT[k*128 + tt] = h2[t0+tt, ks+k]
    __shared__ float BsT[32 * 128];  // BsT[k*128 + mm] = a_q[m0+mm, ks+k]

    const int t  = threadIdx.x;
    const int tx = t & 15;   // m micro-tile
    const int ty = t >> 4;   // token micro-tile
    const int m0 = blockIdx.x * 128;
    const int t0 = blockIdx.y * 128;

    const int ltt = t & 127; // row handled during loads
    const int lk  = t >> 7;  // 0 or 1

    unsigned long long acc2[8][4];
#pragma unroll
    for (int u = 0; u < 8; u++)
#pragma unroll
        for (int v = 0; v < 4; v++) acc2[u][v] = 0ull;

    for (int ks = 0; ks < 64; ks += 32) {
        __syncthreads();
#pragma unroll
        for (int it = 0; it < 4; it++) {
            int kq = lk + it * 2;
            float4 hv = *reinterpret_cast<const float4*>(&g_h2[(t0 + ltt) * 64 + ks + kq * 4]);
            AsT[(kq * 4 + 0) * 128 + ltt] = hv.x;
            AsT[(kq * 4 + 1) * 128 + ltt] = hv.y;
            AsT[(kq * 4 + 2) * 128 + ltt] = hv.z;
            AsT[(kq * 4 + 3) * 128 + ltt] = hv.w;
            float4 av = __ldg(reinterpret_cast<const float4*>(&a_q[(size_t)(m0 + ltt) * 64 + ks + kq * 4]));
            BsT[(kq * 4 + 0) * 128 + ltt] = av.x;
            BsT[(kq * 4 + 1) * 128 + ltt] = av.y;
            BsT[(kq * 4 + 2) * 128 + ltt] = av.z;
            BsT[(kq * 4 + 3) * 128 + ltt] = av.w;
        }
        __syncthreads();

#pragma unroll 8
        for (int k = 0; k < 32; k++) {
            float4 a0 = *reinterpret_cast<const float4*>(&AsT[k * 128 + ty * 8]);
            float4 a1 = *reinterpret_cast<const float4*>(&AsT[k * 128 + ty * 8 + 4]);
            ulonglong2 b0 = *reinterpret_cast<const ulonglong2*>(&BsT[k * 128 + tx * 8]);
            ulonglong2 b1 = *reinterpret_cast<const ulonglong2*>(&BsT[k * 128 + tx * 8 + 4]);
            float ar[8] = {a0.x, a0.y, a0.z, a0.w, a1.x, a1.y, a1.z, a1.w};
#pragma unroll
            for (int u = 0; u < 8; u++) {
                unsigned long long au = dup2(ar[u]);
                acc2[u][0] = ffma2(au, b0.x, acc2[u][0]);
                acc2[u][1] = ffma2(au, b0.y, acc2[u][1]);
                acc2[u][2] = ffma2(au, b1.x, acc2[u][2]);
                acc2[u][3] = ffma2(au, b1.y, acc2[u][3]);
            }
        }
    }

    // epilogue: + bias, float4 stores
    float4 bb0 = __ldg(reinterpret_cast<const float4*>(&bias[m0 + tx * 8]));
    float4 bb1 = __ldg(reinterpret_cast<const float4*>(&bias[m0 + tx * 8 + 4]));
#pragma unroll
    for (int u = 0; u < 8; u++) {
        float* orow = out + (size_t)(t0 + ty * 8 + u) * FEAT + m0 + tx * 8;
        float2 p0 = unpack2(acc2[u][0]);
        float2 p1 = unpack2(acc2[u][1]);
        float2 p2 = unpack2(acc2[u][2]);
        float2 p3 = unpack2(acc2[u][3]);
        float4 o0 = make_float4(p0.x + bb0.x, p0.y + bb0.y, p1.x + bb0.z, p1.y + bb0.w);
        float4 o1 = make_float4(p2.x + bb1.x, p2.y + bb1.y, p3.x + bb1.z, p3.y + bb1.w);
        *reinterpret_cast<float4*>(orow)     = o0;
        *reinterpret_cast<float4*>(orow + 4) = o1;
    }
}

extern "C" void kernel_launch(void* const* d_in, const int* in_sizes, int n_in,
                              void* d_out, int out_size) {
    const float* x      = (const float*)d_in[0];  // (4, 2048, 4096)
    const float* smooth = (const float*)d_in[1];  // (4096,)
    const float* a_q    = (const float*)d_in[2];  // (4096, 64)
    const float* b_q    = (const float*)d_in[3];  // (64, 64)
    const float* c_q_t  = (const float*)d_in[4];  // (64, 64)
    const float* bias   = (const float*)d_in[5];  // (4096,)
    float* out          = (float*)d_out;          // (4, 2048, 4096)

    k1_quant_contract<<<1024, 256>>>(x, smooth, b_q, c_q_t);
    k2_expand<<<dim3(32, 64), 256>>>(a_q, bias, out);
}

// round 3
// speedup vs baseline: 1.1887x; 1.1758x over previous
#include <cuda_runtime.h>

#define TOKENS 8192
#define FEAT   4096

// scratch (device globals -- no allocations allowed)
__device__ __align__(16) float g_h2T[64 * TOKENS];  // [r][tok]  (k-major for k2)
__device__ __align__(16) float g_aT[64 * FEAT];     // [k][m]    (a_q transposed)
__device__ __align__(16) float g_cT[64 * 64];       // [j][r]    (c_q_t transposed)

// ---------------------------------------------------------------------------
// Packed dual-fp32 helpers
// ---------------------------------------------------------------------------
__device__ __forceinline__ unsigned long long ffma2(unsigned long long a,
                                                    unsigned long long b,
                                                    unsigned long long c) {
    unsigned long long d;
    asm("fma.rn.f32x2 %0, %1, %2, %3;" : "=l"(d) : "l"(a), "l"(b), "l"(c));
    return d;
}
__device__ __forceinline__ unsigned long long dup2(float x) {
    unsigned long long r;
    asm("mov.b64 %0, {%1, %1};" : "=l"(r) : "f"(x));
    return r;
}
__device__ __forceinline__ float2 unpack2(unsigned long long v) {
    float lo, hi;
    asm("mov.b64 {%0, %1}, %2;" : "=f"(lo), "=f"(hi) : "l"(v));
    return make_float2(lo, hi);
}

// ---------------------------------------------------------------------------
// kT: transpose a_q (4096x64 -> g_aT 64x4096) and c_q_t (64x64 -> g_cT 64x64).
// Blocks 0..63: a_q 64-row tiles. Block 64: c_q_t.
// ---------------------------------------------------------------------------
__global__ void __launch_bounds__(256) kT_transpose(
    const float* __restrict__ a_q,
    const float* __restrict__ c_q_t)
{
    __shared__ float ts[64 * 65];
    const int t = threadIdx.x;

    const float* src;
    float* dst;
    size_t dstride;
    if (blockIdx.x < 64) {
        src = a_q + (size_t)blockIdx.x * 64 * 64;
        dst = g_aT + blockIdx.x * 64;
        dstride = FEAT;
    } else {
        src = c_q_t;
        dst = g_cT;
        dstride = 64;
    }

#pragma unroll
    for (int it = 0; it < 4; it++) {
        int idx = it * 256 + t;
        int r = idx >> 4, c4 = idx & 15;
        float4 v = __ldg(reinterpret_cast<const float4*>(&src[r * 64 + c4 * 4]));
        ts[r * 65 + c4 * 4 + 0] = v.x;
        ts[r * 65 + c4 * 4 + 1] = v.y;
        ts[r * 65 + c4 * 4 + 2] = v.z;
        ts[r * 65 + c4 * 4 + 3] = v.w;
    }
    __syncthreads();
#pragma unroll
    for (int it = 0; it < 4; it++) {
        int idx = it * 256 + t;
        int k = idx >> 4, m4 = idx & 15;
        float4 w;
        w.x = ts[(m4 * 4 + 0) * 65 + k];
        w.y = ts[(m4 * 4 + 1) * 65 + k];
        w.z = ts[(m4 * 4 + 2) * 65 + k];
        w.w = ts[(m4 * 4 + 3) * 65 + k];
        *reinterpret_cast<float4*>(&dst[(size_t)k * dstride + m4 * 4]) = w;
    }
}

// ---------------------------------------------------------------------------
// k1: smooth + NVFP4 fake-quant + contract C then B -> g_h2T[r][tok]
// ---------------------------------------------------------------------------
#define XQS 68  // padded row stride for xq (2-way worst-case STS conflicts)

__global__ void __launch_bounds__(256, 2) k1_quant_contract(
    const float* __restrict__ x,
    const float* __restrict__ smooth,
    const float* __restrict__ b_q)
{
    __shared__ float csT[64 * 64];    // [j][r]  (from g_cT, conflict-free fill)
    __shared__ float xq[64 * XQS];    // row-major [i][j], stride 68
    __shared__ float red[16 * 64];

    const int t = threadIdx.x;

    for (int idx = t; idx < 4096; idx += 256) csT[idx] = g_cT[idx];

    // thread owns quant block: row qi = t>>2, cols qj0..qj0+15
    float sm[16];
#pragma unroll
    for (int k = 0; k < 4; k++) {
        float4 v = reinterpret_cast<const float4*>(smooth)[t * 4 + k];
        sm[4 * k + 0] = v.x; sm[4 * k + 1] = v.y;
        sm[4 * k + 2] = v.z; sm[4 * k + 3] = v.w;
    }
    __syncthreads();

    const int ti  = t >> 4;
    const int tr  = t & 15;
    const int qi  = t >> 2;
    const int qj0 = (t & 3) * 16;

    int tok = blockIdx.x;
    // first token's x row
    float4 vx[4];
#pragma unroll
    for (int k = 0; k < 4; k++)
        vx[k] = reinterpret_cast<const float4*>(x + (size_t)tok * FEAT)[t * 4 + k];

    for (; tok < TOKENS; tok += gridDim.x) {
        // ---- smooth ----
        float y[16];
#pragma unroll
        for (int k = 0; k < 4; k++) {
            y[4 * k + 0] = vx[k].x * sm[4 * k + 0];
            y[4 * k + 1] = vx[k].y * sm[4 * k + 1];
            y[4 * k + 2] = vx[k].z * sm[4 * k + 2];
            y[4 * k + 3] = vx[k].w * sm[4 * k + 3];
        }

        // ---- NVFP4 fake-quant ----
        float amax = 0.0f;
#pragma unroll
        for (int k = 0; k < 16; k++) amax = fmaxf(amax, fabsf(y[k]));
        float scale = fmaxf(amax / 6.0f, 1e-8f);
        float inv = 1.0f / scale;
        float q[16];
#pragma unroll
        for (int k = 0; k < 16; k++) {
            float av = fabsf(y[k]) * inv;
            float g;
            g = (av <  0.25f) ? 0.0f : 0.5f;
            g = (av >= 0.75f) ? 1.0f : g;
            g = (av >= 1.25f) ? 1.5f : g;
            g = (av >= 1.75f) ? 2.0f : g;
            g = (av >= 2.5f)  ? 3.0f : g;
            g = (av >= 3.5f)  ? 4.0f : g;
            g = (av >= 5.0f)  ? 6.0f : g;
            q[k] = copysignf(g * scale, y[k]);
        }
#pragma unroll
        for (int kk = 0; kk < 4; kk++) {
            float4 s4 = make_float4(q[kk * 4 + 0], q[kk * 4 + 1],
                                    q[kk * 4 + 2], q[kk * 4 + 3]);
            *reinterpret_cast<float4*>(&xq[qi * XQS + qj0 + kk * 4]) = s4;
        }
        __syncthreads();

        // ---- prefetch next token's x (hidden behind stage A/B) ----
        int ntok = tok + gridDim.x;
        if (ntok < TOKENS) {
#pragma unroll
            for (int k = 0; k < 4; k++)
                vx[k] = reinterpret_cast<const float4*>(x + (size_t)ntok * FEAT)[t * 4 + k];
        }

        // ---- stage A: h1[i, r] = sum_j xq[i, j] * C[r, j] ----
        unsigned long long acc2[4][2];
#pragma unroll
        for (int a = 0; a < 4; a++) { acc2[a][0] = 0ull; acc2[a][1] = 0ull; }

#pragma unroll 4
        for (int jc = 0; jc < 16; jc++) {
            float4 xa0 = *reinterpret_cast<const float4*>(&xq[(ti * 4 + 0) * XQS + jc * 4]);
            float4 xa1 = *reinterpret_cast<const float4*>(&xq[(ti * 4 + 1) * XQS + jc * 4]);
            float4 xa2 = *reinterpret_cast<const float4*>(&xq[(ti * 4 + 2) * XQS + jc * 4]);
            float4 xa3 = *reinterpret_cast<const float4*>(&xq[(ti * 4 + 3) * XQS + jc * 4]);
            float xs0[4] = {xa0.x, xa0.y, xa0.z, xa0.w};
            float xs1[4] = {xa1.x, xa1.y, xa1.z, xa1.w};
            float xs2[4] = {xa2.x, xa2.y, xa2.z, xa2.w};
            float xs3[4] = {xa3.x, xa3.y, xa3.z, xa3.w};
#pragma unroll
            for (int d = 0; d < 4; d++) {
                ulonglong2 cv = *reinterpret_cast<const ulonglong2*>(&csT[(jc * 4 + d) * 64 + tr * 4]);
                acc2[0][0] = ffma2(dup2(xs0[d]), cv.x, acc2[0][0]);
                acc2[0][1] = ffma2(dup2(xs0[d]), cv.y, acc2[0][1]);
                acc2[1][0] = ffma2(dup2(xs1[d]), cv.x, acc2[1][0]);
                acc2[1][1] = ffma2(dup2(xs1[d]), cv.y, acc2[1][1]);
                acc2[2][0] = ffma2(dup2(xs2[d]), cv.x, acc2[2][0]);
                acc2[2][1] = ffma2(dup2(xs2[d]), cv.y, acc2[2][1]);
                acc2[3][0] = ffma2(dup2(xs3[d]), cv.x, acc2[3][0]);
                acc2[3][1] = ffma2(dup2(xs3[d]), cv.y, acc2[3][1]);
            }
        }

        // ---- stage B: weight by b_q, partial reduce over i ----
        unsigned long long p0 = 0ull, p1 = 0ull;
#pragma unroll
        for (int a = 0; a < 4; a++) {
            ulonglong2 bv = __ldg(reinterpret_cast<const ulonglong2*>(&b_q[(ti * 4 + a) * 64 + tr * 4]));
            p0 = ffma2(acc2[a][0], bv.x, p0);
            p1 = ffma2(acc2[a][1], bv.y, p1);
        }
        ulonglong2 pr; pr.x = p0; pr.y = p1;
        *reinterpret_cast<ulonglong2*>(&red[ti * 64 + tr * 4]) = pr;
        __syncthreads();

        if (t < 64) {
            float s = 0.0f;
#pragma unroll
            for (int g = 0; g < 16; g++) s += red[g * 64 + t];
            g_h2T[(size_t)t * TOKENS + tok] = s;
        }
    }
}

// ---------------------------------------------------------------------------
// k2: out[t, m] = sum_k h2[t, k] * a_q[m, k] + bias[m]
// 128x128 tile, K=64 in two 32-stages, split 4+4 micro-tiles (conflict-free).
// ---------------------------------------------------------------------------
__global__ void __launch_bounds__(256, 2) k2_expand(
    const float* __restrict__ bias,
    float* __restrict__ out)
{
    __shared__ float AsT[32 * 128];  // [k][token]
    __shared__ float BsT[32 * 128];  // [k][m]

    const int t  = threadIdx.x;
    const int tx = t & 15;   // m: tx*4 and 64+tx*4
    const int ty = t >> 4;   // tok: ty*4 and 64+ty*4
    const int m0 = blockIdx.x * 128;
    const int t0 = blockIdx.y * 128;

    unsigned long long acc2[8][4];
#pragma unroll
    for (int u = 0; u < 8; u++)
#pragma unroll
        for (int v = 0; v < 4; v++) acc2[u][v] = 0ull;

    for (int ks = 0; ks < 64; ks += 32) {
        if (ks) __syncthreads();
#pragma unroll
        for (int it = 0; it < 4; it++) {
            int idx = it * 256 + t;
            int k = idx >> 5, c4 = idx & 31;
            float4 hv = *reinterpret_cast<const float4*>(
                &g_h2T[(size_t)(ks + k) * TOKENS + t0 + c4 * 4]);
            *reinterpret_cast<float4*>(&AsT[k * 128 + c4 * 4]) = hv;
            float4 av = *reinterpret_cast<const float4*>(
                &g_aT[(size_t)(ks + k) * FEAT + m0 + c4 * 4]);
            *reinterpret_cast<float4*>(&BsT[k * 128 + c4 * 4]) = av;
        }
        __syncthreads();

#pragma unroll 8
        for (int k = 0; k < 32; k++) {
            float4 a0 = *reinterpret_cast<const float4*>(&AsT[k * 128 + ty * 4]);
            float4 a1 = *reinterpret_cast<const float4*>(&AsT[k * 128 + 64 + ty * 4]);
            ulonglong2 b0 = *reinterpret_cast<const ulonglong2*>(&BsT[k * 128 + tx * 4]);
            ulonglong2 b1 = *reinterpret_cast<const ulonglong2*>(&BsT[k * 128 + 64 + tx * 4]);
            float ar[8] = {a0.x, a0.y, a0.z, a0.w, a1.x, a1.y, a1.z, a1.w};
#pragma unroll
            for (int u = 0; u < 8; u++) {
                unsigned long long au = dup2(ar[u]);
                acc2[u][0] = ffma2(au, b0.x, acc2[u][0]);
                acc2[u][1] = ffma2(au, b0.y, acc2[u][1]);
                acc2[u][2] = ffma2(au, b1.x, acc2[u][2]);
                acc2[u][3] = ffma2(au, b1.y, acc2[u][3]);
            }
        }
    }

    // epilogue
    float4 bb0 = __ldg(reinterpret_cast<const float4*>(&bias[m0 + tx * 4]));
    float4 bb1 = __ldg(reinterpret_cast<const float4*>(&bias[m0 + 64 + tx * 4]));
#pragma unroll
    for (int u = 0; u < 8; u++) {
        int row = t0 + ((u < 4) ? (ty * 4 + u) : (64 + ty * 4 + (u - 4)));
        float* orow = out + (size_t)row * FEAT + m0;
        float2 p0 = unpack2(acc2[u][0]);
        float2 p1 = unpack2(acc2[u][1]);
        float2 p2 = unpack2(acc2[u][2]);
        float2 p3 = unpack2(acc2[u][3]);
        float4 o0 = make_float4(p0.x + bb0.x, p0.y + bb0.y, p1.x + bb0.z, p1.y + bb0.w);
        float4 o1 = make_float4(p2.x + bb1.x, p2.y + bb1.y, p3.x + bb1.z, p3.y + bb1.w);
        *reinterpret_cast<float4*>(orow + tx * 4)      = o0;
        *reinterpret_cast<float4*>(orow + 64 + tx * 4) = o1;
    }
}

extern "C" void kernel_launch(void* const* d_in, const int* in_sizes, int n_in,
                              void* d_out, int out_size) {
    const float* x      = (const float*)d_in[0];  // (4, 2048, 4096)
    const float* smooth = (const float*)d_in[1];  // (4096,)
    const float* a_q    = (const float*)d_in[2];  // (4096, 64)
    const float* b_q    = (const float*)d_in[3];  // (64, 64)
    const float* c_q_t  = (const float*)d_in[4];  // (64, 64)
    const float* bias   = (const float*)d_in[5];  // (4096,)
    float* out          = (float*)d_out;          // (4, 2048, 4096)

    kT_transpose<<<65, 256>>>(a_q, c_q_t);
    k1_quant_contract<<<1024, 256>>>(x, smooth, b_q);
    k2_expand<<<dim3(32, 64), 256>>>(bias, out);
}